// round 10
// baseline (speedup 1.0000x reference)
#include <cuda_runtime.h>
#include <cuda_bf16.h>
#include <math.h>

// ---------------- problem constants ----------------
#define NN 50000
#define NE 800000
#define NF 32
#define EF 8
#define HEADS 3
#define NG 64
#define G1C 32
#define G2C 16
#define G1O (HEADS*G1C)   // 96
#define G2O (HEADS*G2C)   // 48

// ---------------- device scratch (16B-aligned: vector loads used) ----------------
__device__ __align__(16) float d_h1  [NN*NF];
__device__ __align__(16) float d_h2  [NN*NF];
__device__ __align__(16) float d_prec[NN*128];   // [fD|fS|sD|sS] x32
__device__ __align__(16) float d_bufA[NN*G1O];   // hg
__device__ __align__(16) float d_bufC[NN*G1O];   // layer outputs
__device__ __align__(16) float d_alsrc[NN*4];    // padded to 4 for float4 loads
__device__ __align__(16) float d_aldst[NN*4];
__device__ __align__(16) float d_pool[NG*G2O];
__device__ float d_cnt [NG];
// CSR
__device__ int  d_deg   [NN];
__device__ int  d_rowptr[NN + 1];
__device__ int  d_cursor[NN];
__device__ __align__(16) int2 d_adj[NE];         // (src, edge_id) sorted by dst

// ---------------- utility ----------------
__global__ void fill_f(float* p, float v, int n) {
    int i = blockIdx.x * blockDim.x + threadIdx.x;
    if (i < n) p[i] = v;
}
__global__ void fill_i(int* p, int v, int n) {
    int i = blockIdx.x * blockDim.x + threadIdx.x;
    if (i < n) p[i] = v;
}

// ---------------- CSR construction ----------------
__global__ void csr_hist(const int* __restrict__ dst, int* __restrict__ deg, int E) {
    int i = blockIdx.x * blockDim.x + threadIdx.x;
    if (i < E) atomicAdd(&deg[dst[i]], 1);
}

__global__ __launch_bounds__(1024) void csr_scan(const int* __restrict__ deg,
                                                 int* __restrict__ rowptr,
                                                 int* __restrict__ cursor, int N)
{
    __shared__ int tsum[1024];
    int t = threadIdx.x;
    int per = (N + 1023) / 1024;
    int start = t * per, end = min(start + per, N);
    int s = 0;
    for (int i = start; i < end; i++) s += deg[i];
    tsum[t] = s;
    __syncthreads();
    int inc = s;
    for (int off = 1; off < 1024; off <<= 1) {
        int v = (t >= off) ? tsum[t - off] : 0;
        __syncthreads();
        tsum[t] += v;
        __syncthreads();
    }
    int run = tsum[t] - inc;
    for (int i = start; i < end; i++) {
        rowptr[i] = run; cursor[i] = run;
        run += deg[i];
    }
    if (t == 1023) rowptr[N] = run;
}

__global__ void csr_scatter(const int* __restrict__ src, const int* __restrict__ dst,
                            int* __restrict__ cursor, int2* __restrict__ adj, int E)
{
    int i = blockIdx.x * blockDim.x + threadIdx.x;
    if (i < E) {
        int d = dst[i];
        int pos = atomicAdd(&cursor[d], 1);
        adj[pos] = make_int2(src[i], i);
    }
}

// ---------------- CGConv: node precompute (grid-strided) ----------------
__global__ __launch_bounds__(256) void cg_node_pre(
    const float* __restrict__ x,
    const float* __restrict__ Wf, const float* __restrict__ bf,
    const float* __restrict__ Ws, const float* __restrict__ bs,
    float* __restrict__ prec, int N)
{
    __shared__ float wc[32 * 128];
    for (int idx = threadIdx.x; idx < 32 * 128; idx += 256) {
        int k = idx >> 7, c = idx & 127;
        float v;
        if      (c < 32)  v = Wf[k * 32 + c];
        else if (c < 64)  v = Wf[(32 + k) * 32 + (c - 32)];
        else if (c < 96)  v = Ws[k * 32 + (c - 64)];
        else              v = Ws[(32 + k) * 32 + (c - 96)];
        wc[idx] = v;
    }
    __syncthreads();
    int warp = threadIdx.x >> 5, lane = threadIdx.x & 31;
    int cbase = lane * 4;
    for (int n = blockIdx.x * 8 + warp; n < N; n += gridDim.x * 8) {
        float xv = x[n * 32 + lane];
        float4 acc = make_float4(0.f, 0.f, 0.f, 0.f);
        #pragma unroll
        for (int k = 0; k < 32; k++) {
            float xk = __shfl_sync(0xffffffffu, xv, k);
            float4 w = *(const float4*)&wc[k * 128 + cbase];
            acc.x = fmaf(xk, w.x, acc.x);
            acc.y = fmaf(xk, w.y, acc.y);
            acc.z = fmaf(xk, w.z, acc.z);
            acc.w = fmaf(xk, w.w, acc.w);
        }
        if (cbase < 32) {
            acc.x += bf[cbase]; acc.y += bf[cbase+1]; acc.z += bf[cbase+2]; acc.w += bf[cbase+3];
        } else if (cbase >= 64 && cbase < 96) {
            int b0 = cbase - 64;
            acc.x += bs[b0]; acc.y += bs[b0+1]; acc.z += bs[b0+2]; acc.w += bs[b0+3];
        }
        *(float4*)&prec[n * 128 + cbase] = acc;
    }
}

// ---------------- CGConv: pull aggregation (TWO warps per dst node) ----------------
__global__ __launch_bounds__(256) void cg_pull(
    const float* __restrict__ prec, const float* __restrict__ eattr,
    const int2* __restrict__ adj, const int* __restrict__ rowptr,
    const float* __restrict__ Wf, const float* __restrict__ Ws,
    const float* __restrict__ res, float* __restrict__ out, int N)
{
    __shared__ float wfb[EF * 32], wsb[EF * 32];
    __shared__ float part[4][32];
    int t = threadIdx.x;
    if (t < EF * 32) {
        int k = t >> 5, c = t & 31;
        wfb[t] = Wf[(64 + k) * 32 + c];
        wsb[t] = Ws[(64 + k) * 32 + c];
    }
    __syncthreads();
    int lane = t & 31, warp = t >> 5;
    int pairid = warp >> 1, half = warp & 1;
    int n = blockIdx.x * 4 + pairid;
    bool valid = (n < N);
    float acc = 0.f;
    if (valid) {
        int beg = rowptr[n], endp = rowptr[n + 1];
        int len = endp - beg;
        int mid = beg + ((len + 1) >> 1);
        int lo = half ? mid : beg;
        int hi = half ? endp : mid;
        float fD = prec[n * 128 + lane];
        float sD = prec[n * 128 + 64 + lane];
        #pragma unroll 4
        for (int idx = lo; idx < hi; idx++) {
            int2 se = adj[idx];
            int s = se.x, eid = se.y;
            float f  = fD + __ldg(&prec[s * 128 + 32 + lane]);
            float sv = sD + __ldg(&prec[s * 128 + 96 + lane]);
            float4 ea = *(const float4*)&eattr[eid * EF];
            float4 eb = *(const float4*)&eattr[eid * EF + 4];
            f  = fmaf(ea.x, wfb[0*32+lane], f);  sv = fmaf(ea.x, wsb[0*32+lane], sv);
            f  = fmaf(ea.y, wfb[1*32+lane], f);  sv = fmaf(ea.y, wsb[1*32+lane], sv);
            f  = fmaf(ea.z, wfb[2*32+lane], f);  sv = fmaf(ea.z, wsb[2*32+lane], sv);
            f  = fmaf(ea.w, wfb[3*32+lane], f);  sv = fmaf(ea.w, wsb[3*32+lane], sv);
            f  = fmaf(eb.x, wfb[4*32+lane], f);  sv = fmaf(eb.x, wsb[4*32+lane], sv);
            f  = fmaf(eb.y, wfb[5*32+lane], f);  sv = fmaf(eb.y, wsb[5*32+lane], sv);
            f  = fmaf(eb.z, wfb[6*32+lane], f);  sv = fmaf(eb.z, wsb[6*32+lane], sv);
            f  = fmaf(eb.w, wfb[7*32+lane], f);  sv = fmaf(eb.w, wsb[7*32+lane], sv);
            float sig = 1.f / (1.f + __expf(-f));
            float sp  = fmaxf(sv, 0.f) + __logf(1.f + __expf(-fabsf(sv)));
            acc = fmaf(sig, sp, acc);
        }
    }
    if (half) part[pairid][lane] = acc;
    __syncthreads();
    if (valid && !half) {
        acc += part[pairid][lane];
        out[n * 32 + lane] = fmaxf(acc + res[n * 32 + lane], 0.f);
    }
}

// ---------------- GAT kernels ----------------
template<int IN, int OUT>
__global__ __launch_bounds__(256) void gat_gemm(
    const float* __restrict__ xin, const float* __restrict__ W,
    float* __restrict__ hg, int N)
{
    __shared__ float wsh[IN * OUT];
    __shared__ float xr[8][IN];
    for (int i = threadIdx.x; i < IN * OUT; i += 256) wsh[i] = W[i];
    __syncthreads();
    int warp = threadIdx.x >> 5, lane = threadIdx.x & 31;
    for (int n = blockIdx.x * 8 + warp; n < N; n += gridDim.x * 8) {
        #pragma unroll
        for (int k = lane; k < IN; k += 32) xr[warp][k] = xin[n * IN + k];
        __syncwarp();
        #pragma unroll
        for (int j = 0; j < (OUT + 31) / 32; j++) {
            int c = lane + 32 * j;
            if (c < OUT) {
                float a = 0.f;
                #pragma unroll 8
                for (int k = 0; k < IN; k++) a = fmaf(xr[warp][k], wsh[k * OUT + c], a);
                hg[n * OUT + c] = a;
            }
        }
        __syncwarp();
    }
}

template<int C>
__global__ void gat_al(const float* __restrict__ hg,
                       const float* __restrict__ asrc, const float* __restrict__ adst,
                       float* __restrict__ alsrc, float* __restrict__ aldst, int N)
{
    int i = blockIdx.x * blockDim.x + threadIdx.x;
    if (i >= N * HEADS) return;
    int n = i / HEADS, h = i % HEADS;
    float s = 0.f, d = 0.f;
    #pragma unroll 4
    for (int c = 0; c < C; c++) {
        float v = hg[n * HEADS * C + h * C + c];
        s = fmaf(v, asrc[h * C + c], s);
        d = fmaf(v, adst[h * C + c], d);
    }
    alsrc[n * 4 + h] = s; aldst[n * 4 + h] = d;
}

// Fused pull GAT (shift-free softmax), TWO warps per dst node
template<int OUT, int C>
__global__ __launch_bounds__(256) void gat_pull(
    const float* __restrict__ hg,
    const float* __restrict__ alsrc, const float* __restrict__ aldst,
    const int2* __restrict__ adj, const int* __restrict__ rowptr,
    const float* __restrict__ bias, float* __restrict__ out, int N)
{
    constexpr int J = (OUT + 31) / 32;
    __shared__ float partA[4][J][32];
    __shared__ float partS[4][3];
    int t = threadIdx.x;
    int lane = t & 31, warp = t >> 5;
    int pairid = warp >> 1, half = warp & 1;
    int n = blockIdx.x * 4 + pairid;
    bool valid = (n < N);

    float acc[J];
    #pragma unroll
    for (int j = 0; j < J; j++) acc[j] = 0.f;
    float ss0 = 0.f, ss1 = 0.f, ss2 = 0.f;

    if (valid) {
        float4 adv = *(const float4*)&aldst[n * 4];
        float ad0 = adv.x, ad1 = adv.y, ad2 = adv.z;
        int beg = rowptr[n], endp = rowptr[n + 1];
        int len = endp - beg;
        int mid = beg + ((len + 1) >> 1);
        // even warp also handles the self-loop (idx == beg-1 sentinel)
        int lo = half ? mid : (beg - 1);
        int hi = half ? endp : mid;
        #pragma unroll 4
        for (int idx = lo; idx < hi; idx++) {
            int s = (idx < beg) ? n : adj[idx].x;
            float4 asv = *(const float4*)&alsrc[s * 4];
            float e0 = asv.x + ad0, e1 = asv.y + ad1, e2 = asv.z + ad2;
            e0 = (e0 > 0.f) ? e0 : 0.2f * e0;
            e1 = (e1 > 0.f) ? e1 : 0.2f * e1;
            e2 = (e2 > 0.f) ? e2 : 0.2f * e2;
            float p0 = __expf(e0), p1 = __expf(e1), p2 = __expf(e2);
            ss0 += p0; ss1 += p1; ss2 += p2;
            #pragma unroll
            for (int j = 0; j < J; j++) {
                int c = lane + 32 * j;
                if (c < OUT) {
                    int h = c / C;
                    float pv = (h == 0) ? p0 : ((h == 1) ? p1 : p2);
                    acc[j] = fmaf(__ldg(&hg[s * OUT + c]), pv, acc[j]);
                }
            }
        }
    }
    if (half) {
        #pragma unroll
        for (int j = 0; j < J; j++) partA[pairid][j][lane] = acc[j];
        if (lane == 0) { partS[pairid][0] = ss0; partS[pairid][1] = ss1; partS[pairid][2] = ss2; }
    }
    __syncthreads();
    if (valid && !half) {
        ss0 += partS[pairid][0]; ss1 += partS[pairid][1]; ss2 += partS[pairid][2];
        #pragma unroll
        for (int j = 0; j < J; j++) {
            int c = lane + 32 * j;
            if (c < OUT) {
                int h = c / C;
                float ss = (h == 0) ? ss0 : ((h == 1) ? ss1 : ss2);
                float a = acc[j] + partA[pairid][j][lane];
                out[n * OUT + c] = fmaxf(a / (ss + 1e-16f) + bias[c], 0.f);
            }
        }
    }
}

// ---------------- pooling + head ----------------
__global__ void pool_kernel(const float* __restrict__ g2, const int* __restrict__ batch,
                            float* __restrict__ pooled, float* __restrict__ cnt, int N)
{
    int i = blockIdx.x * blockDim.x + threadIdx.x;
    if (i >= N * G2O) return;
    int n = i / G2O, c = i % G2O;
    int b = batch[n];
    atomicAdd(&pooled[b * G2O + c], g2[i]);
    if (c == 0) atomicAdd(&cnt[b], 1.f);
}

__global__ void head_kernel(const float* __restrict__ pooled, const float* __restrict__ cnt,
                            const float* __restrict__ Wl1, const float* __restrict__ bl1,
                            const float* __restrict__ Wl2, const float* __restrict__ bl2,
                            float* __restrict__ out)
{
    __shared__ float mean[G2O];
    __shared__ float l1[16];
    int g = blockIdx.x, t = threadIdx.x;
    float c = fmaxf(cnt[g], 1.f);
    if (t < G2O) mean[t] = pooled[g * G2O + t] / c;
    __syncthreads();
    if (t < 16) {
        float a = bl1[t];
        #pragma unroll 4
        for (int k = 0; k < G2O; k++) a = fmaf(mean[k], Wl1[k * 16 + t], a);
        l1[t] = fmaxf(a, 0.f);
    }
    __syncthreads();
    if (t < 10) {
        float a = bl2[t];
        #pragma unroll
        for (int k = 0; k < 16; k++) a = fmaf(l1[k], Wl2[k * 10 + t], a);
        out[g * 10 + t] = a;
    }
}

// ---------------- launch ----------------
static inline int cdiv(int a, int b) { return (a + b - 1) / b; }

extern "C" void kernel_launch(void* const* d_in, const int* in_sizes, int n_in,
                              void* d_out, int out_size)
{
    const float* x     = (const float*)d_in[0];
    const float* eattr = (const float*)d_in[1];
    const int*   eidx  = (const int*)  d_in[2];
    const int*   batch = (const int*)  d_in[3];
    const float* Wf1 = (const float*)d_in[4];  const float* bf1 = (const float*)d_in[5];
    const float* Ws1 = (const float*)d_in[6];  const float* bs1 = (const float*)d_in[7];
    const float* Wf2 = (const float*)d_in[8];  const float* bf2 = (const float*)d_in[9];
    const float* Ws2 = (const float*)d_in[10]; const float* bs2 = (const float*)d_in[11];
    const float* Wg1 = (const float*)d_in[12];
    const float* as1 = (const float*)d_in[13]; const float* ad1 = (const float*)d_in[14];
    const float* bg1 = (const float*)d_in[15];
    const float* Wg2 = (const float*)d_in[16];
    const float* as2 = (const float*)d_in[17]; const float* ad2 = (const float*)d_in[18];
    const float* bg2 = (const float*)d_in[19];
    const float* Wl1 = (const float*)d_in[20]; const float* bl1 = (const float*)d_in[21];
    const float* Wl2 = (const float*)d_in[22]; const float* bl2 = (const float*)d_in[23];
    float* out = (float*)d_out;

    const int N = in_sizes[0] / NF;
    const int E = in_sizes[2] / 2;
    const int* src = eidx;
    const int* dst = eidx + E;

    float *h1, *h2, *prec, *bufA, *bufC, *alsrc, *aldst, *pool, *cnt;
    int *deg, *rowptr, *cursor; int2* adj;
    cudaGetSymbolAddress((void**)&h1,   d_h1);
    cudaGetSymbolAddress((void**)&h2,   d_h2);
    cudaGetSymbolAddress((void**)&prec, d_prec);
    cudaGetSymbolAddress((void**)&bufA, d_bufA);
    cudaGetSymbolAddress((void**)&bufC, d_bufC);
    cudaGetSymbolAddress((void**)&alsrc,d_alsrc);
    cudaGetSymbolAddress((void**)&aldst,d_aldst);
    cudaGetSymbolAddress((void**)&pool, d_pool);
    cudaGetSymbolAddress((void**)&cnt,  d_cnt);
    cudaGetSymbolAddress((void**)&deg,    d_deg);
    cudaGetSymbolAddress((void**)&rowptr, d_rowptr);
    cudaGetSymbolAddress((void**)&cursor, d_cursor);
    cudaGetSymbolAddress((void**)&adj,    d_adj);

    const int PAIRB  = cdiv(N, 4);     // 2-warp-per-node pull kernels
    const int GSGRID = 592;            // grid-strided node GEMMs

    // ---- CSR build (reused by all 4 edge passes) ----
    fill_i<<<cdiv(N,256),256>>>(deg, 0, N);
    csr_hist<<<cdiv(E,256),256>>>(dst, deg, E);
    csr_scan<<<1,1024>>>(deg, rowptr, cursor, N);
    csr_scatter<<<cdiv(E,256),256>>>(src, dst, cursor, adj, E);

    // ---- CGConv 1 ----
    cg_node_pre<<<GSGRID,256>>>(x, Wf1, bf1, Ws1, bs1, prec, N);
    cg_pull<<<PAIRB,256>>>(prec, eattr, adj, rowptr, Wf1, Ws1, x, h1, N);

    // ---- CGConv 2 ----
    cg_node_pre<<<GSGRID,256>>>(h1, Wf2, bf2, Ws2, bs2, prec, N);
    cg_pull<<<PAIRB,256>>>(prec, eattr, adj, rowptr, Wf2, Ws2, h1, h2, N);

    // ---- GAT 1 (32 -> 3x32) ----
    gat_gemm<NF, G1O><<<GSGRID,256>>>(h2, Wg1, bufA, N);
    gat_al<G1C><<<cdiv(N*HEADS,256),256>>>(bufA, as1, ad1, alsrc, aldst, N);
    gat_pull<G1O, G1C><<<PAIRB,256>>>(bufA, alsrc, aldst, adj, rowptr, bg1, bufC, N);

    // ---- GAT 2 (96 -> 3x16) ----
    gat_gemm<G1O, G2O><<<GSGRID,256>>>(bufC, Wg2, bufA, N);
    gat_al<G2C><<<cdiv(N*HEADS,256),256>>>(bufA, as2, ad2, alsrc, aldst, N);
    gat_pull<G2O, G2C><<<PAIRB,256>>>(bufA, alsrc, aldst, adj, rowptr, bg2, bufC, N);

    // ---- pool + head ----
    fill_f<<<cdiv(NG*G2O,256),256>>>(pool, 0.f, NG*G2O);
    fill_f<<<1,64>>>(cnt, 0.f, NG);
    pool_kernel<<<cdiv(N*G2O,256),256>>>(bufC, batch, pool, cnt, N);
    head_kernel<<<NG,64>>>(pool, cnt, Wl1, bl1, Wl2, bl2, out);
}

// round 12
// speedup vs baseline: 1.0218x; 1.0218x over previous
#include <cuda_runtime.h>
#include <cuda_bf16.h>
#include <math.h>

// ---------------- problem constants ----------------
#define NN 50000
#define NE 800000
#define NF 32
#define EF 8
#define HEADS 3
#define NG 64
#define G1C 32
#define G2C 16
#define G1O (HEADS*G1C)   // 96
#define G2O (HEADS*G2C)   // 48

// ---------------- device scratch (16B-aligned: vector loads used) ----------------
__device__ __align__(16) float d_h1  [NN*NF];
__device__ __align__(16) float d_h2  [NN*NF];
__device__ __align__(16) float d_prec[NN*128];   // [fD|fS|sD|sS] x32
__device__ __align__(16) float d_bufA[NN*G1O];   // hg
__device__ __align__(16) float d_bufC[NN*G1O];   // layer outputs
__device__ __align__(16) float d_alsrc[NN*4];    // padded to 4 for float4 loads
__device__ __align__(16) float d_aldst[NN*4];
__device__ __align__(16) float d_pool[NG*G2O];
__device__ float d_cnt [NG];
// CSR
__device__ int  d_deg   [NN];
__device__ int  d_rowptr[NN + 1];
__device__ int  d_cursor[NN];
__device__ int  d_adjsrc[NE];                    // src node ids sorted by dst
__device__ __align__(16) float d_eattr_s[NE*EF]; // edge attrs permuted to CSR order

// ---------------- utility ----------------
__global__ void fill_f(float* p, float v, int n) {
    int i = blockIdx.x * blockDim.x + threadIdx.x;
    if (i < n) p[i] = v;
}
__global__ void fill_i(int* p, int v, int n) {
    int i = blockIdx.x * blockDim.x + threadIdx.x;
    if (i < n) p[i] = v;
}

// ---------------- CSR construction ----------------
__global__ void csr_hist(const int* __restrict__ dst, int* __restrict__ deg, int E) {
    int i = blockIdx.x * blockDim.x + threadIdx.x;
    if (i < E) atomicAdd(&deg[dst[i]], 1);
}

__global__ __launch_bounds__(1024) void csr_scan(const int* __restrict__ deg,
                                                 int* __restrict__ rowptr,
                                                 int* __restrict__ cursor, int N)
{
    __shared__ int tsum[1024];
    int t = threadIdx.x;
    int per = (N + 1023) / 1024;
    int start = t * per, end = min(start + per, N);
    int s = 0;
    for (int i = start; i < end; i++) s += deg[i];
    tsum[t] = s;
    __syncthreads();
    int inc = s;
    for (int off = 1; off < 1024; off <<= 1) {
        int v = (t >= off) ? tsum[t - off] : 0;
        __syncthreads();
        tsum[t] += v;
        __syncthreads();
    }
    int run = tsum[t] - inc;
    for (int i = start; i < end; i++) {
        rowptr[i] = run; cursor[i] = run;
        run += deg[i];
    }
    if (t == 1023) rowptr[N] = run;
}

// scatter src ids AND permute edge attributes into CSR order
__global__ void csr_scatter(const int* __restrict__ src, const int* __restrict__ dst,
                            const float* __restrict__ eattr,
                            int* __restrict__ cursor, int* __restrict__ adjsrc,
                            float* __restrict__ eattr_s, int E)
{
    int i = blockIdx.x * blockDim.x + threadIdx.x;
    if (i < E) {
        int d = dst[i];
        int pos = atomicAdd(&cursor[d], 1);
        adjsrc[pos] = src[i];
        float4 a = *(const float4*)&eattr[i * EF];
        float4 b = *(const float4*)&eattr[i * EF + 4];
        *(float4*)&eattr_s[pos * EF]     = a;
        *(float4*)&eattr_s[pos * EF + 4] = b;
    }
}

// ---------------- CGConv: node precompute (grid-strided) ----------------
__global__ __launch_bounds__(256) void cg_node_pre(
    const float* __restrict__ x,
    const float* __restrict__ Wf, const float* __restrict__ bf,
    const float* __restrict__ Ws, const float* __restrict__ bs,
    float* __restrict__ prec, int N)
{
    __shared__ float wc[32 * 128];
    for (int idx = threadIdx.x; idx < 32 * 128; idx += 256) {
        int k = idx >> 7, c = idx & 127;
        float v;
        if      (c < 32)  v = Wf[k * 32 + c];
        else if (c < 64)  v = Wf[(32 + k) * 32 + (c - 32)];
        else if (c < 96)  v = Ws[k * 32 + (c - 64)];
        else              v = Ws[(32 + k) * 32 + (c - 96)];
        wc[idx] = v;
    }
    __syncthreads();
    int warp = threadIdx.x >> 5, lane = threadIdx.x & 31;
    int cbase = lane * 4;
    for (int n = blockIdx.x * 8 + warp; n < N; n += gridDim.x * 8) {
        float xv = x[n * 32 + lane];
        float4 acc = make_float4(0.f, 0.f, 0.f, 0.f);
        #pragma unroll
        for (int k = 0; k < 32; k++) {
            float xk = __shfl_sync(0xffffffffu, xv, k);
            float4 w = *(const float4*)&wc[k * 128 + cbase];
            acc.x = fmaf(xk, w.x, acc.x);
            acc.y = fmaf(xk, w.y, acc.y);
            acc.z = fmaf(xk, w.z, acc.z);
            acc.w = fmaf(xk, w.w, acc.w);
        }
        if (cbase < 32) {
            acc.x += bf[cbase]; acc.y += bf[cbase+1]; acc.z += bf[cbase+2]; acc.w += bf[cbase+3];
        } else if (cbase >= 64 && cbase < 96) {
            int b0 = cbase - 64;
            acc.x += bs[b0]; acc.y += bs[b0+1]; acc.z += bs[b0+2]; acc.w += bs[b0+3];
        }
        *(float4*)&prec[n * 128 + cbase] = acc;
    }
}

// ---------------- CGConv: pull aggregation (warp per dst node) ----------------
__global__ __launch_bounds__(256) void cg_pull(
    const float* __restrict__ prec, const float* __restrict__ eattr_s,
    const int* __restrict__ adjsrc, const int* __restrict__ rowptr,
    const float* __restrict__ Wf, const float* __restrict__ Ws,
    const float* __restrict__ res, float* __restrict__ out, int N)
{
    __shared__ float wfb[EF * 32], wsb[EF * 32];
    int t = threadIdx.x;
    if (t < EF * 32) {
        int k = t >> 5, c = t & 31;
        wfb[t] = Wf[(64 + k) * 32 + c];
        wsb[t] = Ws[(64 + k) * 32 + c];
    }
    __syncthreads();
    int lane = t & 31;
    int n = blockIdx.x * 8 + (t >> 5);
    if (n >= N) return;
    int beg = rowptr[n], endp = rowptr[n + 1];
    float fD = prec[n * 128 + lane];
    float sD = prec[n * 128 + 64 + lane];
    float acc = 0.f;
    #pragma unroll 4
    for (int idx = beg; idx < endp; idx++) {
        int s = __ldg(&adjsrc[idx]);                     // warp-broadcast
        float f  = fD + __ldg(&prec[s * 128 + 32 + lane]);
        float sv = sD + __ldg(&prec[s * 128 + 96 + lane]);
        float4 ea = *(const float4*)&eattr_s[idx * EF];  // sequential stream
        float4 eb = *(const float4*)&eattr_s[idx * EF + 4];
        f  = fmaf(ea.x, wfb[0*32+lane], f);  sv = fmaf(ea.x, wsb[0*32+lane], sv);
        f  = fmaf(ea.y, wfb[1*32+lane], f);  sv = fmaf(ea.y, wsb[1*32+lane], sv);
        f  = fmaf(ea.z, wfb[2*32+lane], f);  sv = fmaf(ea.z, wsb[2*32+lane], sv);
        f  = fmaf(ea.w, wfb[3*32+lane], f);  sv = fmaf(ea.w, wsb[3*32+lane], sv);
        f  = fmaf(eb.x, wfb[4*32+lane], f);  sv = fmaf(eb.x, wsb[4*32+lane], sv);
        f  = fmaf(eb.y, wfb[5*32+lane], f);  sv = fmaf(eb.y, wsb[5*32+lane], sv);
        f  = fmaf(eb.z, wfb[6*32+lane], f);  sv = fmaf(eb.z, wsb[6*32+lane], sv);
        f  = fmaf(eb.w, wfb[7*32+lane], f);  sv = fmaf(eb.w, wsb[7*32+lane], sv);
        float sig = 1.f / (1.f + __expf(-f));
        float sp  = fmaxf(sv, 0.f) + __logf(1.f + __expf(-fabsf(sv)));
        acc = fmaf(sig, sp, acc);
    }
    out[n * 32 + lane] = fmaxf(acc + res[n * 32 + lane], 0.f);
}

// ---------------- GAT kernels ----------------
template<int IN, int OUT>
__global__ __launch_bounds__(256) void gat_gemm(
    const float* __restrict__ xin, const float* __restrict__ W,
    float* __restrict__ hg, int N)
{
    __shared__ float wsh[IN * OUT];
    __shared__ float xr[8][IN];
    for (int i = threadIdx.x; i < IN * OUT; i += 256) wsh[i] = W[i];
    __syncthreads();
    int warp = threadIdx.x >> 5, lane = threadIdx.x & 31;
    for (int n = blockIdx.x * 8 + warp; n < N; n += gridDim.x * 8) {
        #pragma unroll
        for (int k = lane; k < IN; k += 32) xr[warp][k] = xin[n * IN + k];
        __syncwarp();
        #pragma unroll
        for (int j = 0; j < (OUT + 31) / 32; j++) {
            int c = lane + 32 * j;
            if (c < OUT) {
                float a = 0.f;
                #pragma unroll 8
                for (int k = 0; k < IN; k++) a = fmaf(xr[warp][k], wsh[k * OUT + c], a);
                hg[n * OUT + c] = a;
            }
        }
        __syncwarp();
    }
}

template<int C>
__global__ void gat_al(const float* __restrict__ hg,
                       const float* __restrict__ asrc, const float* __restrict__ adst,
                       float* __restrict__ alsrc, float* __restrict__ aldst, int N)
{
    int i = blockIdx.x * blockDim.x + threadIdx.x;
    if (i >= N * HEADS) return;
    int n = i / HEADS, h = i % HEADS;
    float s = 0.f, d = 0.f;
    #pragma unroll 4
    for (int c = 0; c < C; c++) {
        float v = hg[n * HEADS * C + h * C + c];
        s = fmaf(v, asrc[h * C + c], s);
        d = fmaf(v, adst[h * C + c], d);
    }
    alsrc[n * 4 + h] = s; aldst[n * 4 + h] = d;
}

// Fused pull GAT (shift-free softmax), warp per dst node
template<int OUT, int C>
__global__ __launch_bounds__(256) void gat_pull(
    const float* __restrict__ hg,
    const float* __restrict__ alsrc, const float* __restrict__ aldst,
    const int* __restrict__ adjsrc, const int* __restrict__ rowptr,
    const float* __restrict__ bias, float* __restrict__ out, int N)
{
    int lane = threadIdx.x & 31;
    int n = blockIdx.x * 8 + (threadIdx.x >> 5);
    if (n >= N) return;
    float4 adv = *(const float4*)&aldst[n * 4];
    float ad0 = adv.x, ad1 = adv.y, ad2 = adv.z;
    constexpr int J = (OUT + 31) / 32;
    float acc[J];
    #pragma unroll
    for (int j = 0; j < J; j++) acc[j] = 0.f;
    float ss0 = 0.f, ss1 = 0.f, ss2 = 0.f;

    int beg = rowptr[n], endp = rowptr[n + 1];
    #pragma unroll 4
    for (int idx = beg - 1; idx < endp; idx++) {
        int s = (idx < beg) ? n : __ldg(&adjsrc[idx]);   // first iter = self loop
        float4 asv = *(const float4*)&alsrc[s * 4];
        float e0 = asv.x + ad0, e1 = asv.y + ad1, e2 = asv.z + ad2;
        e0 = (e0 > 0.f) ? e0 : 0.2f * e0;
        e1 = (e1 > 0.f) ? e1 : 0.2f * e1;
        e2 = (e2 > 0.f) ? e2 : 0.2f * e2;
        float p0 = __expf(e0), p1 = __expf(e1), p2 = __expf(e2);
        ss0 += p0; ss1 += p1; ss2 += p2;
        #pragma unroll
        for (int j = 0; j < J; j++) {
            int c = lane + 32 * j;
            if (c < OUT) {
                int h = c / C;
                float pv = (h == 0) ? p0 : ((h == 1) ? p1 : p2);
                acc[j] = fmaf(__ldg(&hg[s * OUT + c]), pv, acc[j]);
            }
        }
    }
    #pragma unroll
    for (int j = 0; j < J; j++) {
        int c = lane + 32 * j;
        if (c < OUT) {
            int h = c / C;
            float ss = (h == 0) ? ss0 : ((h == 1) ? ss1 : ss2);
            out[n * OUT + c] = fmaxf(acc[j] / (ss + 1e-16f) + bias[c], 0.f);
        }
    }
}

// ---------------- pooling + head ----------------
__global__ void pool_kernel(const float* __restrict__ g2, const int* __restrict__ batch,
                            float* __restrict__ pooled, float* __restrict__ cnt, int N)
{
    int i = blockIdx.x * blockDim.x + threadIdx.x;
    if (i >= N * G2O) return;
    int n = i / G2O, c = i % G2O;
    int b = batch[n];
    atomicAdd(&pooled[b * G2O + c], g2[i]);
    if (c == 0) atomicAdd(&cnt[b], 1.f);
}

__global__ void head_kernel(const float* __restrict__ pooled, const float* __restrict__ cnt,
                            const float* __restrict__ Wl1, const float* __restrict__ bl1,
                            const float* __restrict__ Wl2, const float* __restrict__ bl2,
                            float* __restrict__ out)
{
    __shared__ float mean[G2O];
    __shared__ float l1[16];
    int g = blockIdx.x, t = threadIdx.x;
    float c = fmaxf(cnt[g], 1.f);
    if (t < G2O) mean[t] = pooled[g * G2O + t] / c;
    __syncthreads();
    if (t < 16) {
        float a = bl1[t];
        #pragma unroll 4
        for (int k = 0; k < G2O; k++) a = fmaf(mean[k], Wl1[k * 16 + t], a);
        l1[t] = fmaxf(a, 0.f);
    }
    __syncthreads();
    if (t < 10) {
        float a = bl2[t];
        #pragma unroll
        for (int k = 0; k < 16; k++) a = fmaf(l1[k], Wl2[k * 10 + t], a);
        out[g * 10 + t] = a;
    }
}

// ---------------- launch ----------------
static inline int cdiv(int a, int b) { return (a + b - 1) / b; }

extern "C" void kernel_launch(void* const* d_in, const int* in_sizes, int n_in,
                              void* d_out, int out_size)
{
    const float* x     = (const float*)d_in[0];
    const float* eattr = (const float*)d_in[1];
    const int*   eidx  = (const int*)  d_in[2];
    const int*   batch = (const int*)  d_in[3];
    const float* Wf1 = (const float*)d_in[4];  const float* bf1 = (const float*)d_in[5];
    const float* Ws1 = (const float*)d_in[6];  const float* bs1 = (const float*)d_in[7];
    const float* Wf2 = (const float*)d_in[8];  const float* bf2 = (const float*)d_in[9];
    const float* Ws2 = (const float*)d_in[10]; const float* bs2 = (const float*)d_in[11];
    const float* Wg1 = (const float*)d_in[12];
    const float* as1 = (const float*)d_in[13]; const float* ad1 = (const float*)d_in[14];
    const float* bg1 = (const float*)d_in[15];
    const float* Wg2 = (const float*)d_in[16];
    const float* as2 = (const float*)d_in[17]; const float* ad2 = (const float*)d_in[18];
    const float* bg2 = (const float*)d_in[19];
    const float* Wl1 = (const float*)d_in[20]; const float* bl1 = (const float*)d_in[21];
    const float* Wl2 = (const float*)d_in[22]; const float* bl2 = (const float*)d_in[23];
    float* out = (float*)d_out;

    const int N = in_sizes[0] / NF;
    const int E = in_sizes[2] / 2;
    const int* src = eidx;
    const int* dst = eidx + E;

    float *h1, *h2, *prec, *bufA, *bufC, *alsrc, *aldst, *pool, *cnt, *eattr_s;
    int *deg, *rowptr, *cursor, *adjsrc;
    cudaGetSymbolAddress((void**)&h1,   d_h1);
    cudaGetSymbolAddress((void**)&h2,   d_h2);
    cudaGetSymbolAddress((void**)&prec, d_prec);
    cudaGetSymbolAddress((void**)&bufA, d_bufA);
    cudaGetSymbolAddress((void**)&bufC, d_bufC);
    cudaGetSymbolAddress((void**)&alsrc,d_alsrc);
    cudaGetSymbolAddress((void**)&aldst,d_aldst);
    cudaGetSymbolAddress((void**)&pool, d_pool);
    cudaGetSymbolAddress((void**)&cnt,  d_cnt);
    cudaGetSymbolAddress((void**)&deg,    d_deg);
    cudaGetSymbolAddress((void**)&rowptr, d_rowptr);
    cudaGetSymbolAddress((void**)&cursor, d_cursor);
    cudaGetSymbolAddress((void**)&adjsrc, d_adjsrc);
    cudaGetSymbolAddress((void**)&eattr_s, d_eattr_s);

    const int NODEB  = cdiv(N, 8);     // warp-per-node pull kernels
    const int GSGRID = 592;            // grid-strided node transforms

    // ---- CSR build (reused by all 4 edge passes) ----
    fill_i<<<cdiv(N,256),256>>>(deg, 0, N);
    csr_hist<<<cdiv(E,256),256>>>(dst, deg, E);
    csr_scan<<<1,1024>>>(deg, rowptr, cursor, N);
    csr_scatter<<<cdiv(E,256),256>>>(src, dst, eattr, cursor, adjsrc, eattr_s, E);

    // ---- CGConv 1 ----
    cg_node_pre<<<GSGRID,256>>>(x, Wf1, bf1, Ws1, bs1, prec, N);
    cg_pull<<<NODEB,256>>>(prec, eattr_s, adjsrc, rowptr, Wf1, Ws1, x, h1, N);

    // ---- CGConv 2 ----
    cg_node_pre<<<GSGRID,256>>>(h1, Wf2, bf2, Ws2, bs2, prec, N);
    cg_pull<<<NODEB,256>>>(prec, eattr_s, adjsrc, rowptr, Wf2, Ws2, h1, h2, N);

    // ---- GAT 1 (32 -> 3x32) ----
    gat_gemm<NF, G1O><<<GSGRID,256>>>(h2, Wg1, bufA, N);
    gat_al<G1C><<<cdiv(N*HEADS,256),256>>>(bufA, as1, ad1, alsrc, aldst, N);
    gat_pull<G1O, G1C><<<NODEB,256>>>(bufA, alsrc, aldst, adjsrc, rowptr, bg1, bufC, N);

    // ---- GAT 2 (96 -> 3x16) ----
    gat_gemm<G1O, G2O><<<GSGRID,256>>>(bufC, Wg2, bufA, N);
    gat_al<G2C><<<cdiv(N*HEADS,256),256>>>(bufA, as2, ad2, alsrc, aldst, N);
    gat_pull<G2O, G2C><<<NODEB,256>>>(bufA, alsrc, aldst, adjsrc, rowptr, bg2, bufC, N);

    // ---- pool + head ----
    fill_f<<<cdiv(NG*G2O,256),256>>>(pool, 0.f, NG*G2O);
    fill_f<<<1,64>>>(cnt, 0.f, NG);
    pool_kernel<<<cdiv(N*G2O,256),256>>>(bufC, batch, pool, cnt, N);
    head_kernel<<<NG,64>>>(pool, cnt, Wl1, bl1, Wl2, bl2, out);
}

// round 14
// speedup vs baseline: 1.0592x; 1.0366x over previous
#include <cuda_runtime.h>
#include <cuda_bf16.h>
#include <math.h>

// ---------------- problem constants ----------------
#define NN 50000
#define NE 800000
#define NF 32
#define EF 8
#define HEADS 3
#define NG 64
#define G1C 32
#define G2C 16
#define G1O (HEADS*G1C)   // 96
#define G2O (HEADS*G2C)   // 48

// ---------------- device scratch (16B-aligned: vector loads used) ----------------
__device__ __align__(16) float d_h1  [NN*NF];
__device__ __align__(16) float d_h2  [NN*NF];
// prec layout (interleaved pairs):
//   [n*128 + 2c]   = fD_c   [n*128 + 2c+1]   = sD_c      (c = 0..31)
//   [n*128 +64+2c] = fS_c   [n*128 +64+2c+1] = sS_c
__device__ __align__(16) float d_prec[NN*128];
__device__ __align__(16) float d_bufA[NN*G1O];   // hg
__device__ __align__(16) float d_bufC[NN*G1O];   // layer outputs
__device__ __align__(16) float d_alsrc[NN*4];    // padded to 4 for float4 loads
__device__ __align__(16) float d_aldst[NN*4];
__device__ __align__(16) float d_pool[NG*G2O];
__device__ float d_cnt [NG];
// CSR
__device__ int  d_deg   [NN];
__device__ int  d_rowptr[NN + 1];
__device__ int  d_cursor[NN];
__device__ int  d_adjsrc[NE];                    // src node ids sorted by dst
__device__ __align__(16) float d_eattr_s[NE*EF]; // edge attrs permuted to CSR order

// ---------------- utility ----------------
__global__ void fill_f(float* p, float v, int n) {
    int i = blockIdx.x * blockDim.x + threadIdx.x;
    if (i < n) p[i] = v;
}
__global__ void fill_i(int* p, int v, int n) {
    int i = blockIdx.x * blockDim.x + threadIdx.x;
    if (i < n) p[i] = v;
}

// ---------------- CSR construction ----------------
__global__ void csr_hist(const int* __restrict__ dst, int* __restrict__ deg, int E) {
    int i = blockIdx.x * blockDim.x + threadIdx.x;
    if (i < E) atomicAdd(&deg[dst[i]], 1);
}

__global__ __launch_bounds__(1024) void csr_scan(const int* __restrict__ deg,
                                                 int* __restrict__ rowptr,
                                                 int* __restrict__ cursor, int N)
{
    __shared__ int tsum[1024];
    int t = threadIdx.x;
    int per = (N + 1023) / 1024;
    int start = t * per, end = min(start + per, N);
    int s = 0;
    for (int i = start; i < end; i++) s += deg[i];
    tsum[t] = s;
    __syncthreads();
    int inc = s;
    for (int off = 1; off < 1024; off <<= 1) {
        int v = (t >= off) ? tsum[t - off] : 0;
        __syncthreads();
        tsum[t] += v;
        __syncthreads();
    }
    int run = tsum[t] - inc;
    for (int i = start; i < end; i++) {
        rowptr[i] = run; cursor[i] = run;
        run += deg[i];
    }
    if (t == 1023) rowptr[N] = run;
}

// scatter src ids AND permute edge attributes into CSR order
__global__ void csr_scatter(const int* __restrict__ src, const int* __restrict__ dst,
                            const float* __restrict__ eattr,
                            int* __restrict__ cursor, int* __restrict__ adjsrc,
                            float* __restrict__ eattr_s, int E)
{
    int i = blockIdx.x * blockDim.x + threadIdx.x;
    if (i < E) {
        int d = dst[i];
        int pos = atomicAdd(&cursor[d], 1);
        adjsrc[pos] = src[i];
        float4 a = *(const float4*)&eattr[i * EF];
        float4 b = *(const float4*)&eattr[i * EF + 4];
        *(float4*)&eattr_s[pos * EF]     = a;
        *(float4*)&eattr_s[pos * EF + 4] = b;
    }
}

// ---------------- CGConv: node precompute (grid-strided, interleaved output) -----
__global__ __launch_bounds__(256) void cg_node_pre(
    const float* __restrict__ x,
    const float* __restrict__ Wf, const float* __restrict__ bf,
    const float* __restrict__ Ws, const float* __restrict__ bs,
    float* __restrict__ prec, int N)
{
    __shared__ float wc[32 * 128];
    // combined weights in interleaved layout: out col m:
    //   c = ((m<64)? m : m-64) >> 1 ; odd m -> Ws, even -> Wf ; m>=64 -> src-half rows
    for (int idx = threadIdx.x; idx < 32 * 128; idx += 256) {
        int k = idx >> 7, m = idx & 127;
        int c = ((m < 64) ? m : (m - 64)) >> 1;
        int row = (m < 64) ? k : (32 + k);
        float v = (m & 1) ? Ws[row * 32 + c] : Wf[row * 32 + c];
        wc[idx] = v;
    }
    __syncthreads();
    int warp = threadIdx.x >> 5, lane = threadIdx.x & 31;
    int cbase = lane * 4;
    for (int n = blockIdx.x * 8 + warp; n < N; n += gridDim.x * 8) {
        float xv = x[n * 32 + lane];
        float4 acc = make_float4(0.f, 0.f, 0.f, 0.f);
        #pragma unroll
        for (int k = 0; k < 32; k++) {
            float xk = __shfl_sync(0xffffffffu, xv, k);
            float4 w = *(const float4*)&wc[k * 128 + cbase];
            acc.x = fmaf(xk, w.x, acc.x);
            acc.y = fmaf(xk, w.y, acc.y);
            acc.z = fmaf(xk, w.z, acc.z);
            acc.w = fmaf(xk, w.w, acc.w);
        }
        if (cbase < 64) {      // dst-half gets biases: even=bf, odd=bs
            int c0 = cbase >> 1;
            acc.x += bf[c0]; acc.y += bs[c0]; acc.z += bf[c0 + 1]; acc.w += bs[c0 + 1];
        }
        *(float4*)&prec[n * 128 + cbase] = acc;
    }
}

// ---------------- CGConv: pull aggregation (warp per dst node) ----------------
// weights for edge-attr part held in registers; src gather = single float2
__global__ __launch_bounds__(256) void cg_pull(
    const float* __restrict__ prec, const float* __restrict__ eattr_s,
    const int* __restrict__ adjsrc, const int* __restrict__ rowptr,
    const float* __restrict__ Wf, const float* __restrict__ Ws,
    const float* __restrict__ res, float* __restrict__ out, int N)
{
    int t = threadIdx.x;
    int lane = t & 31;
    // hoisted edge-attr weights (bottom 8 rows of Wf / Ws), 16 registers
    float wf0 = Wf[(64+0)*32+lane], wf1 = Wf[(64+1)*32+lane];
    float wf2 = Wf[(64+2)*32+lane], wf3 = Wf[(64+3)*32+lane];
    float wf4 = Wf[(64+4)*32+lane], wf5 = Wf[(64+5)*32+lane];
    float wf6 = Wf[(64+6)*32+lane], wf7 = Wf[(64+7)*32+lane];
    float ws0 = Ws[(64+0)*32+lane], ws1 = Ws[(64+1)*32+lane];
    float ws2 = Ws[(64+2)*32+lane], ws3 = Ws[(64+3)*32+lane];
    float ws4 = Ws[(64+4)*32+lane], ws5 = Ws[(64+5)*32+lane];
    float ws6 = Ws[(64+6)*32+lane], ws7 = Ws[(64+7)*32+lane];

    int n = blockIdx.x * 8 + (t >> 5);
    if (n >= N) return;
    int beg = rowptr[n], endp = rowptr[n + 1];
    float2 dv = *(const float2*)&prec[n * 128 + 2 * lane];   // (fD, sD)
    float acc = 0.f;
    #pragma unroll 4
    for (int idx = beg; idx < endp; idx++) {
        int s = __ldg(&adjsrc[idx]);                              // warp-broadcast
        float2 g = __ldg((const float2*)&prec[s * 128 + 64 + 2 * lane]); // (fS, sS)
        float f  = dv.x + g.x;
        float sv = dv.y + g.y;
        float4 ea = *(const float4*)&eattr_s[idx * EF];           // sequential stream
        float4 eb = *(const float4*)&eattr_s[idx * EF + 4];
        f  = fmaf(ea.x, wf0, f);  sv = fmaf(ea.x, ws0, sv);
        f  = fmaf(ea.y, wf1, f);  sv = fmaf(ea.y, ws1, sv);
        f  = fmaf(ea.z, wf2, f);  sv = fmaf(ea.z, ws2, sv);
        f  = fmaf(ea.w, wf3, f);  sv = fmaf(ea.w, ws3, sv);
        f  = fmaf(eb.x, wf4, f);  sv = fmaf(eb.x, ws4, sv);
        f  = fmaf(eb.y, wf5, f);  sv = fmaf(eb.y, ws5, sv);
        f  = fmaf(eb.z, wf6, f);  sv = fmaf(eb.z, ws6, sv);
        f  = fmaf(eb.w, wf7, f);  sv = fmaf(eb.w, ws7, sv);
        float sig = 1.f / (1.f + __expf(-f));
        float sp  = fmaxf(sv, 0.f) + __logf(1.f + __expf(-fabsf(sv)));
        acc = fmaf(sig, sp, acc);
    }
    out[n * 32 + lane] = fmaxf(acc + res[n * 32 + lane], 0.f);
}

// ---------------- GAT kernels ----------------
template<int IN, int OUT>
__global__ __launch_bounds__(256) void gat_gemm(
    const float* __restrict__ xin, const float* __restrict__ W,
    float* __restrict__ hg, int N)
{
    __shared__ float wsh[IN * OUT];
    __shared__ float xr[8][IN];
    for (int i = threadIdx.x; i < IN * OUT; i += 256) wsh[i] = W[i];
    __syncthreads();
    int warp = threadIdx.x >> 5, lane = threadIdx.x & 31;
    for (int n = blockIdx.x * 8 + warp; n < N; n += gridDim.x * 8) {
        #pragma unroll
        for (int k = lane; k < IN; k += 32) xr[warp][k] = xin[n * IN + k];
        __syncwarp();
        #pragma unroll
        for (int j = 0; j < (OUT + 31) / 32; j++) {
            int c = lane + 32 * j;
            if (c < OUT) {
                float a = 0.f;
                #pragma unroll 8
                for (int k = 0; k < IN; k++) a = fmaf(xr[warp][k], wsh[k * OUT + c], a);
                hg[n * OUT + c] = a;
            }
        }
        __syncwarp();
    }
}

template<int C>
__global__ void gat_al(const float* __restrict__ hg,
                       const float* __restrict__ asrc, const float* __restrict__ adst,
                       float* __restrict__ alsrc, float* __restrict__ aldst, int N)
{
    int i = blockIdx.x * blockDim.x + threadIdx.x;
    if (i >= N * HEADS) return;
    int n = i / HEADS, h = i % HEADS;
    float s = 0.f, d = 0.f;
    #pragma unroll 4
    for (int c = 0; c < C; c++) {
        float v = hg[n * HEADS * C + h * C + c];
        s = fmaf(v, asrc[h * C + c], s);
        d = fmaf(v, adst[h * C + c], d);
    }
    alsrc[n * 4 + h] = s; aldst[n * 4 + h] = d;
}

// Fused pull GAT (shift-free softmax), warp per dst node
template<int OUT, int C>
__global__ __launch_bounds__(256) void gat_pull(
    const float* __restrict__ hg,
    const float* __restrict__ alsrc, const float* __restrict__ aldst,
    const int* __restrict__ adjsrc, const int* __restrict__ rowptr,
    const float* __restrict__ bias, float* __restrict__ out, int N)
{
    int lane = threadIdx.x & 31;
    int n = blockIdx.x * 8 + (threadIdx.x >> 5);
    if (n >= N) return;
    float4 adv = *(const float4*)&aldst[n * 4];
    float ad0 = adv.x, ad1 = adv.y, ad2 = adv.z;
    constexpr int J = (OUT + 31) / 32;
    float acc[J];
    #pragma unroll
    for (int j = 0; j < J; j++) acc[j] = 0.f;
    float ss0 = 0.f, ss1 = 0.f, ss2 = 0.f;

    int beg = rowptr[n], endp = rowptr[n + 1];
    #pragma unroll 4
    for (int idx = beg - 1; idx < endp; idx++) {
        int s = (idx < beg) ? n : __ldg(&adjsrc[idx]);   // first iter = self loop
        float4 asv = *(const float4*)&alsrc[s * 4];
        float e0 = asv.x + ad0, e1 = asv.y + ad1, e2 = asv.z + ad2;
        e0 = (e0 > 0.f) ? e0 : 0.2f * e0;
        e1 = (e1 > 0.f) ? e1 : 0.2f * e1;
        e2 = (e2 > 0.f) ? e2 : 0.2f * e2;
        float p0 = __expf(e0), p1 = __expf(e1), p2 = __expf(e2);
        ss0 += p0; ss1 += p1; ss2 += p2;
        #pragma unroll
        for (int j = 0; j < J; j++) {
            int c = lane + 32 * j;
            if (c < OUT) {
                int h = c / C;
                float pv = (h == 0) ? p0 : ((h == 1) ? p1 : p2);
                acc[j] = fmaf(__ldg(&hg[s * OUT + c]), pv, acc[j]);
            }
        }
    }
    #pragma unroll
    for (int j = 0; j < J; j++) {
        int c = lane + 32 * j;
        if (c < OUT) {
            int h = c / C;
            float ss = (h == 0) ? ss0 : ((h == 1) ? ss1 : ss2);
            out[n * OUT + c] = fmaxf(acc[j] / (ss + 1e-16f) + bias[c], 0.f);
        }
    }
}

// ---------------- pooling + head ----------------
__global__ void pool_kernel(const float* __restrict__ g2, const int* __restrict__ batch,
                            float* __restrict__ pooled, float* __restrict__ cnt, int N)
{
    int i = blockIdx.x * blockDim.x + threadIdx.x;
    if (i >= N * G2O) return;
    int n = i / G2O, c = i % G2O;
    int b = batch[n];
    atomicAdd(&pooled[b * G2O + c], g2[i]);
    if (c == 0) atomicAdd(&cnt[b], 1.f);
}

__global__ void head_kernel(const float* __restrict__ pooled, const float* __restrict__ cnt,
                            const float* __restrict__ Wl1, const float* __restrict__ bl1,
                            const float* __restrict__ Wl2, const float* __restrict__ bl2,
                            float* __restrict__ out)
{
    __shared__ float mean[G2O];
    __shared__ float l1[16];
    int g = blockIdx.x, t = threadIdx.x;
    float c = fmaxf(cnt[g], 1.f);
    if (t < G2O) mean[t] = pooled[g * G2O + t] / c;
    __syncthreads();
    if (t < 16) {
        float a = bl1[t];
        #pragma unroll 4
        for (int k = 0; k < G2O; k++) a = fmaf(mean[k], Wl1[k * 16 + t], a);
        l1[t] = fmaxf(a, 0.f);
    }
    __syncthreads();
    if (t < 10) {
        float a = bl2[t];
        #pragma unroll
        for (int k = 0; k < 16; k++) a = fmaf(l1[k], Wl2[k * 10 + t], a);
        out[g * 10 + t] = a;
    }
}

// ---------------- launch ----------------
static inline int cdiv(int a, int b) { return (a + b - 1) / b; }

extern "C" void kernel_launch(void* const* d_in, const int* in_sizes, int n_in,
                              void* d_out, int out_size)
{
    const float* x     = (const float*)d_in[0];
    const float* eattr = (const float*)d_in[1];
    const int*   eidx  = (const int*)  d_in[2];
    const int*   batch = (const int*)  d_in[3];
    const float* Wf1 = (const float*)d_in[4];  const float* bf1 = (const float*)d_in[5];
    const float* Ws1 = (const float*)d_in[6];  const float* bs1 = (const float*)d_in[7];
    const float* Wf2 = (const float*)d_in[8];  const float* bf2 = (const float*)d_in[9];
    const float* Ws2 = (const float*)d_in[10]; const float* bs2 = (const float*)d_in[11];
    const float* Wg1 = (const float*)d_in[12];
    const float* as1 = (const float*)d_in[13]; const float* ad1 = (const float*)d_in[14];
    const float* bg1 = (const float*)d_in[15];
    const float* Wg2 = (const float*)d_in[16];
    const float* as2 = (const float*)d_in[17]; const float* ad2 = (const float*)d_in[18];
    const float* bg2 = (const float*)d_in[19];
    const float* Wl1 = (const float*)d_in[20]; const float* bl1 = (const float*)d_in[21];
    const float* Wl2 = (const float*)d_in[22]; const float* bl2 = (const float*)d_in[23];
    float* out = (float*)d_out;

    const int N = in_sizes[0] / NF;
    const int E = in_sizes[2] / 2;
    const int* src = eidx;
    const int* dst = eidx + E;

    float *h1, *h2, *prec, *bufA, *bufC, *alsrc, *aldst, *pool, *cnt, *eattr_s;
    int *deg, *rowptr, *cursor, *adjsrc;
    cudaGetSymbolAddress((void**)&h1,   d_h1);
    cudaGetSymbolAddress((void**)&h2,   d_h2);
    cudaGetSymbolAddress((void**)&prec, d_prec);
    cudaGetSymbolAddress((void**)&bufA, d_bufA);
    cudaGetSymbolAddress((void**)&bufC, d_bufC);
    cudaGetSymbolAddress((void**)&alsrc,d_alsrc);
    cudaGetSymbolAddress((void**)&aldst,d_aldst);
    cudaGetSymbolAddress((void**)&pool, d_pool);
    cudaGetSymbolAddress((void**)&cnt,  d_cnt);
    cudaGetSymbolAddress((void**)&deg,    d_deg);
    cudaGetSymbolAddress((void**)&rowptr, d_rowptr);
    cudaGetSymbolAddress((void**)&cursor, d_cursor);
    cudaGetSymbolAddress((void**)&adjsrc, d_adjsrc);
    cudaGetSymbolAddress((void**)&eattr_s, d_eattr_s);

    const int NODEB  = cdiv(N, 8);     // warp-per-node pull kernels
    const int GSGRID = 592;            // grid-strided node transforms

    // ---- CSR build (reused by all 4 edge passes) ----
    fill_i<<<cdiv(N,256),256>>>(deg, 0, N);
    csr_hist<<<cdiv(E,256),256>>>(dst, deg, E);
    csr_scan<<<1,1024>>>(deg, rowptr, cursor, N);
    csr_scatter<<<cdiv(E,256),256>>>(src, dst, eattr, cursor, adjsrc, eattr_s, E);

    // ---- CGConv 1 ----
    cg_node_pre<<<GSGRID,256>>>(x, Wf1, bf1, Ws1, bs1, prec, N);
    cg_pull<<<NODEB,256>>>(prec, eattr_s, adjsrc, rowptr, Wf1, Ws1, x, h1, N);

    // ---- CGConv 2 ----
    cg_node_pre<<<GSGRID,256>>>(h1, Wf2, bf2, Ws2, bs2, prec, N);
    cg_pull<<<NODEB,256>>>(prec, eattr_s, adjsrc, rowptr, Wf2, Ws2, h1, h2, N);

    // ---- GAT 1 (32 -> 3x32) ----
    gat_gemm<NF, G1O><<<GSGRID,256>>>(h2, Wg1, bufA, N);
    gat_al<G1C><<<cdiv(N*HEADS,256),256>>>(bufA, as1, ad1, alsrc, aldst, N);
    gat_pull<G1O, G1C><<<NODEB,256>>>(bufA, alsrc, aldst, adjsrc, rowptr, bg1, bufC, N);

    // ---- GAT 2 (96 -> 3x16) ----
    gat_gemm<G1O, G2O><<<GSGRID,256>>>(bufC, Wg2, bufA, N);
    gat_al<G2C><<<cdiv(N*HEADS,256),256>>>(bufA, as2, ad2, alsrc, aldst, N);
    gat_pull<G2O, G2C><<<NODEB,256>>>(bufA, alsrc, aldst, adjsrc, rowptr, bg2, bufC, N);

    // ---- pool + head ----
    fill_f<<<cdiv(NG*G2O,256),256>>>(pool, 0.f, NG*G2O);
    fill_f<<<1,64>>>(cnt, 0.f, NG);
    pool_kernel<<<cdiv(N*G2O,256),256>>>(bufC, batch, pool, cnt, N);
    head_kernel<<<NG,64>>>(pool, cnt, Wl1, bl1, Wl2, bl2, out);
}